// round 9
// baseline (speedup 1.0000x reference)
#include <cuda_runtime.h>

#define GN 512
#define GBATCH 16
#define RSTRIP 8
#define MAXITER 20
#define KFUSE 4
#define WARMUP 6

// Scratch ping-pong buffer (16 MB) — __device__ global, no runtime allocation.
__device__ float g_scratch[GBATCH * GN * GN];

__device__ __forceinline__ float4 ld4(const float* p) {
    return *reinterpret_cast<const float4*>(p);
}
__device__ __forceinline__ float4 ld4r(const float* p, int row, int col) {
    return ((unsigned)row < GN) ? ld4(p + row * GN + col)
                                : make_float4(0.f, 0.f, 0.f, 0.f);
}

// In-tile Jacobi row update: horizontal neighbors via shuffles, tile-edge
// values eL (lane 0) / eR (lane 31) injected by caller.
__device__ __forceinline__ float4 jrow(float4 up, float4 mid, float4 dn, float4 bv,
                                       float eL, float eR, int lane)
{
    float l = __shfl_up_sync(0xffffffffu, mid.w, 1);
    float r = __shfl_down_sync(0xffffffffu, mid.x, 1);
    if (lane == 0)  l = eL;
    if (lane == 31) r = eR;
    float4 res;
    res.x = 0.25f * (bv.x + l     + mid.y + up.x + dn.x);
    res.y = 0.25f * (bv.y + mid.x + mid.z + up.y + dn.y);
    res.z = 0.25f * (bv.z + mid.y + mid.w + up.z + dn.z);
    res.w = 0.25f * (bv.w + mid.z + r     + up.w + dn.w);
    return res;
}

// Edge Jacobi row update on the extra float4 just outside the tile.
// left edge (lane 0):  cols [wcb-4, wcb-1]; inner = in-tile col wcb.
// right edge (lane 31): cols [wcb+128, wcb+131]; inner = in-tile col wcb+127.
// Only applied on ep lanes; elsewhere edge state stays exactly zero.
__device__ __forceinline__ float4 erow(float4 up, float4 mid, float4 dn, float4 bv,
                                       float inner, bool left)
{
    float4 res;
    res.x = left ? 0.f : 0.25f * (bv.x + inner + mid.y + up.x + dn.x);
    res.y = 0.25f * (bv.y + mid.x + mid.z + up.y + dn.y);
    res.z = 0.25f * (bv.z + mid.y + mid.w + up.z + dn.z);
    res.w = left ? 0.25f * (bv.w + mid.z + inner + up.w + dn.w) : 0.f;
    return res;
}

// Four fused Jacobi sweeps, register-marching down an RSTRIP-row strip.
// Warps fully independent; edge columns recomputed via a float4 pipeline
// in lockstep with the in-tile pipeline. No smem, no barriers.
// CRITICAL: every level is computed ONLY for real rows 0..GN-1 (two-sided
// guard) — virtual rows above and below the grid must stay exactly zero.
// src_sel: 0 = u, 1 = g_scratch, 2 = out ; dst_sel: 0 = out, 1 = g_scratch
__global__ void __launch_bounds__(128) jacobi4(
    const float* __restrict__ u,
    const float* __restrict__ b,
    float* __restrict__ out,
    int src_sel, int dst_sel)
{
    const float* x = (src_sel == 0) ? u
                   : (src_sel == 1) ? (const float*)g_scratch
                                    : (const float*)out;
    float* o = dst_sel ? g_scratch : out;

    const int lane = threadIdx.x & 31;
    const int w    = threadIdx.x >> 5;          // warp 0..3 -> cols [w*128, w*128+128)
    const int wcb  = w * 128;
    const int c    = wcb + lane * 4;
    const int r0   = blockIdx.x * RSTRIP;
    const size_t base = (size_t)blockIdx.y * (GN * GN);
    const float* xg = x + base;
    const float* bg = b + base;
    float*       og = o + base;

    const float4 Z = make_float4(0.f, 0.f, 0.f, 0.f);

    const bool left = (lane == 0);
    const bool ep   = (left && w > 0) || (lane == 31 && w < 3);
    const int ebase = left ? (wcb - 4) : (wcb + 128);   // edge float4 base col

    // ---- prologue: x rows r0-4, r0-3 (tile + edge); pipelines zero ----
    float4 xm  = ld4r(xg, r0 - 4, c);
    float4 xc  = ld4r(xg, r0 - 3, c);
    float4 xEm = ep ? ld4r(xg, r0 - 4, ebase) : Z;
    float4 xEc = ep ? ld4r(xg, r0 - 3, ebase) : Z;

    float4 pm1 = Z, pc1 = Z, pm2 = Z, pc2 = Z, pm3 = Z, pc3 = Z;
    float4 E1m = Z, E1c = Z, E2m = Z, E2c = Z, E3c = Z;
    float4 bL2 = Z, bL3 = Z, bL4 = Z, bE2 = Z, bE3 = Z;

    // ---- march: t=-WARMUP..RSTRIP-1; store output row i = r0+t when t>=0 ----
    #pragma unroll
    for (int t = -WARMUP; t < RSTRIP; ++t) {
        const int i  = r0 + t;
        const int rx = i + 4;     // x row loaded this step
        const int rb = i + 3;     // b row loaded / level-1 row computed

        float4 xp  = ld4r(xg, rx, c);
        float4 bL1 = ld4r(bg, rb, c);
        float4 xEp = ep ? ld4r(xg, rx, ebase) : Z;
        float4 bEn = ep ? ld4r(bg, rb, ebase) : Z;

        // level 1 at row rb (= i+3); ONLY for real rows (two-sided guard)
        float4 pn1 = Z, E1n = Z;
        if ((unsigned)rb < GN) {
            pn1 = jrow(xm, xc, xp, bL1, xEc.w, xEc.x, lane);
            if (ep) E1n = erow(xEm, xEc, xEp, bEn, left ? xc.x : xc.w, left);
        }

        // level 2 at row i+2
        float4 pn2 = Z, E2n = Z;
        if ((unsigned)(i + 2) < GN) {
            pn2 = jrow(pm1, pc1, pn1, bL2, E1c.w, E1c.x, lane);
            if (ep) E2n = erow(E1m, E1c, E1n, bE2, left ? pc1.x : pc1.w, left);
        }

        // level 3 at row i+1
        float4 pn3 = Z, E3n = Z;
        if ((unsigned)(i + 1) < GN) {
            pn3 = jrow(pm2, pc2, pn2, bL3, E2c.w, E2c.x, lane);
            if (ep) E3n = erow(E2m, E2c, E2n, bE3, left ? pc2.x : pc2.w, left);
        }

        // level 4 (output) at row i
        if (t >= 0) {
            float4 res = jrow(pm3, pc3, pn3, bL4, E3c.w, E3c.x, lane);
            *reinterpret_cast<float4*>(og + i * GN + c) = res;
        }

        // lockstep shifts
        xm  = xc;  xc  = xp;   xEm = xEc; xEc = xEp;
        pm1 = pc1; pc1 = pn1;  E1m = E1c; E1c = E1n;
        pm2 = pc2; pc2 = pn2;  E2m = E2c; E2c = E2n;
        pm3 = pc3; pc3 = pn3;  E3c = E3n;
        bL4 = bL3; bL3 = bL2;  bL2 = bL1;
        bE3 = bE2; bE2 = bEn;
    }
}

extern "C" void kernel_launch(void* const* d_in, const int* in_sizes, int n_in,
                              void* d_out, int out_size)
{
    const float* u = (const float*)d_in[0];
    const float* b = (const float*)d_in[1];
    float* out = (float*)d_out;

    dim3 block(128);                       // 4 independent warps (4 col tiles)
    dim3 grid(GN / RSTRIP, GBATCH);        // 64 strips x 16 batches = 1024 blocks

    const int nfused = MAXITER / KFUSE;    // 5 launches, 4 sweeps each
    int prev_dst = -1;
    for (int f = 0; f < nfused; ++f) {
        int dst = ((nfused - 1 - f) & 1);             // last one lands in out
        int src = (f == 0) ? 0 : (prev_dst ? 1 : 2);
        jacobi4<<<grid, block>>>(u, b, out, src, dst);
        prev_dst = dst;
    }
}

// round 11
// speedup vs baseline: 1.1476x; 1.1476x over previous
#include <cuda_runtime.h>

#define GN 512
#define GBATCH 16
#define RSTRIP 16
#define NSTRIPS (GN / RSTRIP)     // 32
#define TILE_OUT 112              // output cols per warp tile
#define NTILES 5                  // 5*112 = 560 >= 512
#define MAXITER 20
#define KFUSE 4
#define WARMUP 6

// Scratch ping-pong buffer (16 MB) — __device__ global, no runtime allocation.
__device__ float g_scratch[GBATCH * GN * GN];

__device__ __forceinline__ float4 ld4(const float* p) {
    return *reinterpret_cast<const float4*>(p);
}
// Masked tile load: zero outside real rows [0,GN) or outside valid columns.
__device__ __forceinline__ float4 ld4m(const float* p, int row, int cbase, bool vc) {
    return (vc && (unsigned)row < GN) ? ld4(p + row * GN + cbase)
                                      : make_float4(0.f, 0.f, 0.f, 0.f);
}

// Jacobi row update on a 128-col register row (float4/lane). No lane fixups:
// lanes 0/31 produce garbage at the tile's outermost cols; it lies in the
// 8-col overlap margin and is never stored (garbage moves 1 col per sweep).
__device__ __forceinline__ float4 jrow(float4 up, float4 mid, float4 dn, float4 bv) {
    float l = __shfl_up_sync(0xffffffffu, mid.w, 1);
    float r = __shfl_down_sync(0xffffffffu, mid.x, 1);
    float4 res;
    res.x = 0.25f * (bv.x + l     + mid.y + up.x + dn.x);
    res.y = 0.25f * (bv.y + mid.x + mid.z + up.y + dn.y);
    res.z = 0.25f * (bv.z + mid.y + mid.w + up.z + dn.z);
    res.w = 0.25f * (bv.w + mid.z + r     + up.w + dn.w);
    return res;
}

// Four fused Jacobi sweeps; register-marching; fully independent warps via
// overlapped column tiles (load 128 cols, store central 112). No smem, no
// barriers, no divergent edge paths.
// CRITICAL guards (learned rounds 8 & 10): every level's result must be
// exactly zero for virtual rows (two-sided row guard) AND for out-of-grid
// column lanes (vc guard) — virtual cells outside the grid must never hold
// computed values, or boundary columns/rows absorb phantom contributions.
// src_sel: 0 = u, 1 = g_scratch, 2 = out ; dst_sel: 0 = out, 1 = g_scratch
__global__ void __launch_bounds__(128) jacobi4(
    const float* __restrict__ u,
    const float* __restrict__ b,
    float* __restrict__ out,
    int src_sel, int dst_sel)
{
    const float* x = (src_sel == 0) ? u
                   : (src_sel == 1) ? (const float*)g_scratch
                                    : (const float*)out;
    float* o = dst_sel ? g_scratch : out;

    const int lane  = threadIdx.x & 31;
    const int wid   = threadIdx.x >> 5;
    const int strip = blockIdx.x * 4 + wid;        // 0..31
    const int r0    = strip * RSTRIP;
    const int tb    = blockIdx.y * TILE_OUT;       // tile output base col
    const int cbase = tb - 8 + lane * 4;           // this lane's float4 col
    const bool vc   = (cbase >= 0) && (cbase <= GN - 4);          // lane fully in grid
    const bool vs   = (lane >= 2) && (lane <= 29) && (cbase <= GN - 4); // store mask

    const size_t base = (size_t)blockIdx.z * (GN * GN);
    const float* xg = x + base;
    const float* bg = b + base;
    float*       og = o + base;

    const float4 Z = make_float4(0.f, 0.f, 0.f, 0.f);

    // ---- prologue: x rows r0-4, r0-3; pipelines zero ----
    float4 xm = ld4m(xg, r0 - 4, cbase, vc);
    float4 xc = ld4m(xg, r0 - 3, cbase, vc);

    float4 pm1 = Z, pc1 = Z, pm2 = Z, pc2 = Z, pm3 = Z, pc3 = Z;
    float4 bL2 = Z, bL3 = Z, bL4 = Z;

    // ---- march: t=-WARMUP..RSTRIP-1; store output row i = r0+t when t>=0 ----
    #pragma unroll
    for (int t = -WARMUP; t < RSTRIP; ++t) {
        const int i  = r0 + t;
        const int rx = i + 4;     // x row loaded this step
        const int rb = i + 3;     // b row loaded / level-1 row computed

        float4 xp  = ld4m(xg, rx, cbase, vc);
        float4 bL1 = ld4m(bg, rb, cbase, vc);

        // level 1 at row rb (= i+3): real rows AND in-grid columns only
        float4 pn1 = (vc && (unsigned)rb < GN)      ? jrow(xm, xc, xp, bL1)    : Z;
        // level 2 at row i+2
        float4 pn2 = (vc && (unsigned)(i + 2) < GN) ? jrow(pm1, pc1, pn1, bL2) : Z;
        // level 3 at row i+1
        float4 pn3 = (vc && (unsigned)(i + 1) < GN) ? jrow(pm2, pc2, pn2, bL3) : Z;

        // level 4 (output) at row i
        if (t >= 0) {
            float4 res = jrow(pm3, pc3, pn3, bL4);
            if (vs) *reinterpret_cast<float4*>(og + i * GN + cbase) = res;
        }

        // lockstep shifts
        xm  = xc;  xc  = xp;
        pm1 = pc1; pc1 = pn1;
        pm2 = pc2; pc2 = pn2;
        pm3 = pc3; pc3 = pn3;
        bL4 = bL3; bL3 = bL2; bL2 = bL1;
    }
}

extern "C" void kernel_launch(void* const* d_in, const int* in_sizes, int n_in,
                              void* d_out, int out_size)
{
    const float* u = (const float*)d_in[0];
    const float* b = (const float*)d_in[1];
    float* out = (float*)d_out;

    dim3 block(128);                           // 4 independent warps (4 strips)
    dim3 grid(NSTRIPS / 4, NTILES, GBATCH);    // 8 x 5 x 16 = 640 blocks

    const int nfused = MAXITER / KFUSE;        // 5 launches, 4 sweeps each
    int prev_dst = -1;
    for (int f = 0; f < nfused; ++f) {
        int dst = ((nfused - 1 - f) & 1);              // last one lands in out
        int src = (f == 0) ? 0 : (prev_dst ? 1 : 2);
        jacobi4<<<grid, block>>>(u, b, out, src, dst);
        prev_dst = dst;
    }
}

// round 12
// speedup vs baseline: 1.2111x; 1.0553x over previous
#include <cuda_runtime.h>

#define GN 512
#define GBATCH 16
#define RSTRIP 16
#define NSTRIPS (GN / RSTRIP)     // 32
#define TILE_OUT 112              // output cols per warp tile
#define NTILES 5                  // 5*112 = 560 >= 512
#define MAXITER 20
#define KFUSE 4
#define WARMUP 6

// Scratch ping-pong buffer (16 MB) — __device__ global, no runtime allocation.
__device__ float g_scratch[GBATCH * GN * GN];

__device__ __forceinline__ float4 ld4(const float* p) {
    return *reinterpret_cast<const float4*>(p);
}
// Masked tile load: zero outside real rows [0,GN) or outside valid columns.
__device__ __forceinline__ float4 ld4m(const float* p, int row, int cbase, bool vc) {
    return (vc && (unsigned)row < GN) ? ld4(p + row * GN + cbase)
                                      : make_float4(0.f, 0.f, 0.f, 0.f);
}
__device__ __forceinline__ float4 scale4(float4 v) {
    v.x *= 0.25f; v.y *= 0.25f; v.z *= 0.25f; v.w *= 0.25f;
    return v;
}

// Jacobi row update; b4 is PRE-SCALED by 0.25 so each element is
// 3 FADD + 1 FFMA. Lanes 0/31 produce garbage at the tile's outermost cols;
// it lies in the 8-col overlap margin and is never stored.
__device__ __forceinline__ float4 jrowf(float4 up, float4 mid, float4 dn, float4 b4) {
    float l = __shfl_up_sync(0xffffffffu, mid.w, 1);
    float r = __shfl_down_sync(0xffffffffu, mid.x, 1);
    float4 res;
    res.x = fmaf((l     + mid.y) + (up.x + dn.x), 0.25f, b4.x);
    res.y = fmaf((mid.x + mid.z) + (up.y + dn.y), 0.25f, b4.y);
    res.z = fmaf((mid.y + mid.w) + (up.z + dn.z), 0.25f, b4.z);
    res.w = fmaf((mid.z + r    ) + (up.w + dn.w), 0.25f, b4.w);
    return res;
}

// Four fused Jacobi sweeps; register-marching; fully independent warps via
// overlapped column tiles (load 128 cols, store central 112).
// Interior blocks (rows and cols all real) run a guard-free fast path —
// warm-up depth 6 provably confines Z-seeded garbage to discarded rows.
// Boundary blocks run the guarded path: every level's result forced to zero
// for virtual rows (two-sided) and out-of-grid column lanes.
// src_sel: 0 = u, 1 = g_scratch, 2 = out ; dst_sel: 0 = out, 1 = g_scratch
__global__ void __launch_bounds__(128) jacobi4(
    const float* __restrict__ u,
    const float* __restrict__ b,
    float* __restrict__ out,
    int src_sel, int dst_sel)
{
    const float* x = (src_sel == 0) ? u
                   : (src_sel == 1) ? (const float*)g_scratch
                                    : (const float*)out;
    float* o = dst_sel ? g_scratch : out;

    const int lane  = threadIdx.x & 31;
    const int wid   = threadIdx.x >> 5;
    const int strip = blockIdx.x * 4 + wid;        // 0..31
    const int r0    = strip * RSTRIP;
    const int tb    = blockIdx.y * TILE_OUT;       // tile output base col
    const int cbase = tb - 8 + lane * 4;           // this lane's float4 col
    const bool vc   = (cbase >= 0) && (cbase <= GN - 4);
    const bool vs   = (lane >= 2) && (lane <= 29) && (cbase <= GN - 4);

    const size_t base = (size_t)blockIdx.z * (GN * GN);
    const float* xg = x + base;
    const float* bg = b + base;
    float*       og = o + base;

    const float4 Z = make_float4(0.f, 0.f, 0.f, 0.f);

    // Interior: all touched rows (r0-4 .. r0+RSTRIP+3) real AND all lanes'
    // columns in-grid (tiles 1..NTILES-2).
    const bool fast = (r0 >= 4) && (r0 <= GN - RSTRIP - 4) &&
                      (blockIdx.y > 0) && (blockIdx.y < NTILES - 1);

    if (fast) {
        // ---- guard-free path: unpredicated loads, no SELs ----
        float4 xm = ld4(xg + (r0 - 4) * GN + cbase);
        float4 xc = ld4(xg + (r0 - 3) * GN + cbase);
        float4 pm1 = Z, pc1 = Z, pm2 = Z, pc2 = Z, pm3 = Z, pc3 = Z;
        float4 bL2 = Z, bL3 = Z, bL4 = Z;

        #pragma unroll
        for (int t = -WARMUP; t < RSTRIP; ++t) {
            const int i = r0 + t;
            float4 xp  = ld4(xg + (i + 4) * GN + cbase);
            float4 bL1 = scale4(ld4(bg + (i + 3) * GN + cbase));

            float4 pn1 = jrowf(xm, xc, xp, bL1);
            float4 pn2 = jrowf(pm1, pc1, pn1, bL2);
            float4 pn3 = jrowf(pm2, pc2, pn2, bL3);
            if (t >= 0) {
                float4 res = jrowf(pm3, pc3, pn3, bL4);
                if (vs) *reinterpret_cast<float4*>(og + i * GN + cbase) = res;
            }
            xm  = xc;  xc  = xp;
            pm1 = pc1; pc1 = pn1;
            pm2 = pc2; pc2 = pn2;
            pm3 = pc3; pc3 = pn3;
            bL4 = bL3; bL3 = bL2; bL2 = bL1;
        }
    } else {
        // ---- guarded path (round-11 semantics, proven correct) ----
        float4 xm = ld4m(xg, r0 - 4, cbase, vc);
        float4 xc = ld4m(xg, r0 - 3, cbase, vc);
        float4 pm1 = Z, pc1 = Z, pm2 = Z, pc2 = Z, pm3 = Z, pc3 = Z;
        float4 bL2 = Z, bL3 = Z, bL4 = Z;

        #pragma unroll
        for (int t = -WARMUP; t < RSTRIP; ++t) {
            const int i  = r0 + t;
            const int rx = i + 4;
            const int rb = i + 3;

            float4 xp  = ld4m(xg, rx, cbase, vc);
            float4 bL1 = scale4(ld4m(bg, rb, cbase, vc));

            float4 pn1 = (vc && (unsigned)rb < GN)      ? jrowf(xm, xc, xp, bL1)    : Z;
            float4 pn2 = (vc && (unsigned)(i + 2) < GN) ? jrowf(pm1, pc1, pn1, bL2) : Z;
            float4 pn3 = (vc && (unsigned)(i + 1) < GN) ? jrowf(pm2, pc2, pn2, bL3) : Z;

            if (t >= 0) {
                float4 res = jrowf(pm3, pc3, pn3, bL4);
                if (vs) *reinterpret_cast<float4*>(og + i * GN + cbase) = res;
            }
            xm  = xc;  xc  = xp;
            pm1 = pc1; pc1 = pn1;
            pm2 = pc2; pc2 = pn2;
            pm3 = pc3; pc3 = pn3;
            bL4 = bL3; bL3 = bL2; bL2 = bL1;
        }
    }
}

extern "C" void kernel_launch(void* const* d_in, const int* in_sizes, int n_in,
                              void* d_out, int out_size)
{
    const float* u = (const float*)d_in[0];
    const float* b = (const float*)d_in[1];
    float* out = (float*)d_out;

    dim3 block(128);                           // 4 independent warps (4 strips)
    dim3 grid(NSTRIPS / 4, NTILES, GBATCH);    // 8 x 5 x 16 = 640 blocks

    const int nfused = MAXITER / KFUSE;        // 5 launches, 4 sweeps each
    int prev_dst = -1;
    for (int f = 0; f < nfused; ++f) {
        int dst = ((nfused - 1 - f) & 1);              // last one lands in out
        int src = (f == 0) ? 0 : (prev_dst ? 1 : 2);
        jacobi4<<<grid, block>>>(u, b, out, src, dst);
        prev_dst = dst;
    }
}

// round 13
// speedup vs baseline: 1.4015x; 1.1572x over previous
#include <cuda_runtime.h>

#define GN 512
#define GBATCH 16
#define RSTRIP 16
#define NSTRIPS 32                // GN / RSTRIP
#define NTILES 5                  // windows at 0,96,192,288,384 (all in-grid)
#define MAXITER 20
#define KFUSE 4
#define WARMUP 9                  // level skew 2 -> first store at t=9
#define NSTEPS (RSTRIP + WARMUP)  // 25

// Scratch ping-pong buffer (16 MB) — __device__ global, no runtime allocation.
__device__ float g_scratch[GBATCH * GN * GN];

__device__ __forceinline__ float4 ld4(const float* p) {
    return *reinterpret_cast<const float4*>(p);
}
template<bool G>
__device__ __forceinline__ float4 ldx(const float* p, int row, int cbase) {
    if (G) return ((unsigned)row < GN) ? ld4(p + row * GN + cbase)
                                       : make_float4(0.f, 0.f, 0.f, 0.f);
    return ld4(p + row * GN + cbase);
}
__device__ __forceinline__ float4 scale4(float4 v) {
    v.x *= 0.25f; v.y *= 0.25f; v.z *= 0.25f; v.w *= 0.25f;
    return v;
}

// Jacobi row update; b4 PRE-SCALED by 0.25. Lane 0's left / lane 31's right
// neighbor is forced to 0: exact Dirichlet at real grid-edge windows, and
// harmless inside the >=4-col discard margin at internal window seams.
__device__ __forceinline__ float4 jrowf(float4 up, float4 mid, float4 dn,
                                        float4 b4, int lane)
{
    float l = __shfl_up_sync(0xffffffffu, mid.w, 1);
    float r = __shfl_down_sync(0xffffffffu, mid.x, 1);
    if (lane == 0)  l = 0.f;
    if (lane == 31) r = 0.f;
    float4 res;
    res.x = fmaf((l     + mid.y) + (up.x + dn.x), 0.25f, b4.x);
    res.y = fmaf((mid.x + mid.z) + (up.y + dn.y), 0.25f, b4.y);
    res.z = fmaf((mid.y + mid.w) + (up.z + dn.z), 0.25f, b4.z);
    res.w = fmaf((mid.z + r    ) + (up.w + dn.w), 0.25f, b4.w);
    return res;
}

// Level-skewed 4-deep Jacobi pipeline. At step t (a = r0-3+t):
//   load x[a+1], b[a];  L1 -> row a;  L2 -> row a-2;  L3 -> row a-4;
//   L4 (store) -> row a-6, from t >= WARMUP.
// Each level consumes only values produced at steps <= t-1 (ring depth 3),
// so all four jrowf calls per step are independent (ILP=4, no serial
// shuffle chain). Z-initialized rings feed only rows below the correctness
// wavefront (L2 valid >= r0-2, L3 >= r0-1, stored output >= r0).
// G=true adds two-sided row guards on loads and every level (strips 0/31).
template<bool G>
__device__ __forceinline__ void march(const float* __restrict__ xg,
                                      const float* __restrict__ bg,
                                      float* __restrict__ og,
                                      int r0, int cbase, bool vs, int lane)
{
    const float4 Z = make_float4(0.f, 0.f, 0.f, 0.f);

    float4 xm = ldx<G>(xg, r0 - 4, cbase);   // x row a-1 at t=0
    float4 xc = ldx<G>(xg, r0 - 3, cbase);   // x row a   at t=0

    float4 p1b = Z, p1c = Z, p1d = Z;        // L1 rows a-1, a-2, a-3
    float4 p2b = Z, p2c = Z, p2d = Z;        // L2 rows a-3, a-4, a-5
    float4 p3b = Z, p3c = Z, p3d = Z;        // L3 rows a-5, a-6, a-7
    float4 br1 = Z, br2 = Z, br3 = Z, br4 = Z, br5 = Z, br6 = Z; // b[a-1..a-6]

    #pragma unroll
    for (int t = 0; t < NSTEPS; ++t) {
        const int a = r0 - 3 + t;

        float4 xp = ldx<G>(xg, a + 1, cbase);
        float4 b0 = scale4(ldx<G>(bg, a, cbase));

        // four INDEPENDENT level updates (inputs all from steps <= t-1)
        float4 pn1 = (!G || (unsigned)a < GN)
                   ? jrowf(xm, xc, xp, b0, lane) : Z;          // L1 row a
        float4 pn2 = (!G || (unsigned)(a - 2) < GN)
                   ? jrowf(p1d, p1c, p1b, br2, lane) : Z;      // L2 row a-2
        float4 pn3 = (!G || (unsigned)(a - 4) < GN)
                   ? jrowf(p2d, p2c, p2b, br4, lane) : Z;      // L3 row a-4

        if (t >= WARMUP) {                                     // L4 row a-6
            float4 res = jrowf(p3d, p3c, p3b, br6, lane);
            if (vs) *reinterpret_cast<float4*>(og + (a - 6) * GN + cbase) = res;
        }

        // lockstep ring shifts (renamed by ptxas, no real MOVs)
        xm = xc; xc = xp;
        p1d = p1c; p1c = p1b; p1b = pn1;
        p2d = p2c; p2c = p2b; p2b = pn2;
        p3d = p3c; p3c = p3b; p3b = pn3;
        br6 = br5; br5 = br4; br4 = br3; br3 = br2; br2 = br1; br1 = b0;
    }
}

// src_sel: 0 = u, 1 = g_scratch, 2 = out ; dst_sel: 0 = out, 1 = g_scratch
__global__ void __launch_bounds__(128) jacobi4(
    const float* __restrict__ u,
    const float* __restrict__ b,
    float* __restrict__ out,
    int src_sel, int dst_sel)
{
    const float* x = (src_sel == 0) ? u
                   : (src_sel == 1) ? (const float*)g_scratch
                                    : (const float*)out;
    float* o = dst_sel ? g_scratch : out;

    const int lane  = threadIdx.x & 31;
    const int wid   = threadIdx.x >> 5;
    const int strip = blockIdx.x * 4 + wid;         // 0..31
    const int r0    = strip * RSTRIP;
    const int ty    = blockIdx.y;
    const int wb    = ty * 96;                      // window base: 0..384
    const int cbase = wb + lane * 4;                // ALWAYS in [0, 508]
    const int slo   = (ty == 0)          ? 0  : wb + 4;
    const int shi   = (ty == NTILES - 1) ? GN : wb + 100;
    const bool vs   = (cbase >= slo) && (cbase < shi);

    const size_t base = (size_t)blockIdx.z * (GN * GN);
    const float* xg = x + base;
    const float* bg = b + base;
    float*       og = o + base;

    // rows touched: r0-4 .. r0+RSTRIP+6; guard only strips 0 and 31
    if ((r0 >= 4) && (r0 + RSTRIP + 6 < GN))
        march<false>(xg, bg, og, r0, cbase, vs, lane);
    else
        march<true >(xg, bg, og, r0, cbase, vs, lane);
}

extern "C" void kernel_launch(void* const* d_in, const int* in_sizes, int n_in,
                              void* d_out, int out_size)
{
    const float* u = (const float*)d_in[0];
    const float* b = (const float*)d_in[1];
    float* out = (float*)d_out;

    dim3 block(128);                           // 4 independent warps (4 strips)
    dim3 grid(NSTRIPS / 4, NTILES, GBATCH);    // 8 x 5 x 16 = 640 blocks

    const int nfused = MAXITER / KFUSE;        // 5 launches, 4 sweeps each
    int prev_dst = -1;
    for (int f = 0; f < nfused; ++f) {
        int dst = ((nfused - 1 - f) & 1);              // last one lands in out
        int src = (f == 0) ? 0 : (prev_dst ? 1 : 2);
        jacobi4<<<grid, block>>>(u, b, out, src, dst);
        prev_dst = dst;
    }
}

// round 14
// speedup vs baseline: 1.4729x; 1.0510x over previous
#include <cuda_runtime.h>

#define GN 512
#define GBATCH 16
#define RSTRIP 16
#define NSTRIPS 32                // GN / RSTRIP
#define NTILES 5                  // windows at 0,96,192,288,384 (all in-grid)
#define MAXITER 20
#define KFUSE 4
#define WARMUP 9                  // level skew 2 -> first store at t=9
#define NSTEPS (RSTRIP + WARMUP)  // 25

// Scratch ping-pong buffer (16 MB) — __device__ global, no runtime allocation.
__device__ float g_scratch[GBATCH * GN * GN];

__device__ __forceinline__ float4 ld4(const float* p) {
    return *reinterpret_cast<const float4*>(p);
}
template<bool G>
__device__ __forceinline__ float4 ldx(const float* p, int row, int cbase) {
    if (G) return ((unsigned)row < GN) ? ld4(p + row * GN + cbase)
                                       : make_float4(0.f, 0.f, 0.f, 0.f);
    return ld4(p + row * GN + cbase);
}
__device__ __forceinline__ float4 scale4(float4 v) {
    v.x *= 0.25f; v.y *= 0.25f; v.z *= 0.25f; v.w *= 0.25f;
    return v;
}

// Jacobi row update; b4 PRE-SCALED by 0.25. Lane 0's left / lane 31's right
// neighbor is forced to 0: exact Dirichlet at grid-edge windows, harmless
// inside the >=4-col discard margin at internal window seams.
__device__ __forceinline__ float4 jrowf(float4 up, float4 mid, float4 dn,
                                        float4 b4, int lane)
{
    float l = __shfl_up_sync(0xffffffffu, mid.w, 1);
    float r = __shfl_down_sync(0xffffffffu, mid.x, 1);
    if (lane == 0)  l = 0.f;
    if (lane == 31) r = 0.f;
    float4 res;
    res.x = fmaf((l     + mid.y) + (up.x + dn.x), 0.25f, b4.x);
    res.y = fmaf((mid.x + mid.z) + (up.y + dn.y), 0.25f, b4.y);
    res.z = fmaf((mid.y + mid.w) + (up.z + dn.z), 0.25f, b4.z);
    res.w = fmaf((mid.z + r    ) + (up.w + dn.w), 0.25f, b4.w);
    return res;
}

// Level-skewed (skew 2) 4-deep Jacobi pipeline with 2-step load prefetch.
// At step t (a = r0-3+t): prefetch x[a+3], b[a+2] (used at t+2);
// L1 -> row a (consumes x prefetched 2 steps ago); L2 -> row a-2;
// L3 -> row a-4; L4 (store) -> row a-6 from t >= WARMUP.
// Lagged b rows (a-2, a-4, a-6) are RE-LOADED from L1 (this warp fetched
// those lines 2-8 steps earlier) instead of held in a 6-deep register ring.
// All four level updates per step are mutually independent (inputs from
// steps <= t-1). Z-initialized rings feed only discarded rows.
// G=true adds two-sided row guards on loads and every level (strips 0/31).
template<bool G>
__device__ __forceinline__ void march(const float* __restrict__ xg,
                                      const float* __restrict__ bg,
                                      float* __restrict__ og,
                                      int r0, int cbase, bool vs, int lane)
{
    const float4 Z = make_float4(0.f, 0.f, 0.f, 0.f);

    float4 xm  = ldx<G>(xg, r0 - 4, cbase);              // x row a-1 @ t=0
    float4 xc  = ldx<G>(xg, r0 - 3, cbase);              // x row a   @ t=0
    float4 xp0 = ldx<G>(xg, r0 - 2, cbase);              // x row a+1 for t=0
    float4 bb0 = scale4(ldx<G>(bg, r0 - 3, cbase));      // b row a   for t=0
    float4 xp1 = ldx<G>(xg, r0 - 1, cbase);              // for t=1
    float4 bb1 = scale4(ldx<G>(bg, r0 - 2, cbase));      // for t=1

    float4 p1b = Z, p1c = Z, p1d = Z;        // L1 rows a-1, a-2, a-3
    float4 p2b = Z, p2c = Z, p2d = Z;        // L2 rows a-3, a-4, a-5
    float4 p3b = Z, p3c = Z, p3d = Z;        // L3 rows a-5, a-6, a-7

    #pragma unroll
    for (int t = 0; t < NSTEPS; ++t) {
        const int a = r0 - 3 + t;

        // prefetch for step t+2 (issued ~2 steps before use)
        float4 xp2 = ldx<G>(xg, a + 3, cbase);
        float4 bb2 = scale4(ldx<G>(bg, a + 2, cbase));

        // lagged b rows from L1 (lines fetched by this warp steps ago)
        float4 b2 = scale4(ldx<G>(bg, a - 2, cbase));
        float4 b4 = scale4(ldx<G>(bg, a - 4, cbase));

        // four INDEPENDENT level updates (inputs all from steps <= t-1)
        float4 pn1 = (!G || (unsigned)a < GN)
                   ? jrowf(xm, xc, xp0, bb0, lane) : Z;        // L1 row a
        float4 pn2 = (!G || (unsigned)(a - 2) < GN)
                   ? jrowf(p1d, p1c, p1b, b2, lane) : Z;       // L2 row a-2
        float4 pn3 = (!G || (unsigned)(a - 4) < GN)
                   ? jrowf(p2d, p2c, p2b, b4, lane) : Z;       // L3 row a-4

        if (t >= WARMUP) {                                     // L4 row a-6
            float4 b6 = scale4(ldx<G>(bg, a - 6, cbase));
            float4 res = jrowf(p3d, p3c, p3b, b6, lane);
            if (vs) *reinterpret_cast<float4*>(og + (a - 6) * GN + cbase) = res;
        }

        // lockstep ring shifts (renamed by ptxas, no real MOVs)
        xm = xc; xc = xp0; xp0 = xp1; xp1 = xp2;
        bb0 = bb1; bb1 = bb2;
        p1d = p1c; p1c = p1b; p1b = pn1;
        p2d = p2c; p2c = p2b; p2b = pn2;
        p3d = p3c; p3c = p3b; p3b = pn3;
    }
}

// src_sel: 0 = u, 1 = g_scratch, 2 = out ; dst_sel: 0 = out, 1 = g_scratch
__global__ void __launch_bounds__(128, 5) jacobi4(
    const float* __restrict__ u,
    const float* __restrict__ b,
    float* __restrict__ out,
    int src_sel, int dst_sel)
{
    const float* x = (src_sel == 0) ? u
                   : (src_sel == 1) ? (const float*)g_scratch
                                    : (const float*)out;
    float* o = dst_sel ? g_scratch : out;

    const int lane  = threadIdx.x & 31;
    const int wid   = threadIdx.x >> 5;
    const int strip = blockIdx.x * 4 + wid;         // 0..31
    const int r0    = strip * RSTRIP;
    const int ty    = blockIdx.y;
    const int wb    = ty * 96;                      // window base: 0..384
    const int cbase = wb + lane * 4;                // ALWAYS in [0, 508]
    const int slo   = (ty == 0)          ? 0  : wb + 4;
    const int shi   = (ty == NTILES - 1) ? GN : wb + 100;
    const bool vs   = (cbase >= slo) && (cbase < shi);

    const size_t base = (size_t)blockIdx.z * (GN * GN);
    const float* xg = x + base;
    const float* bg = b + base;
    float*       og = o + base;

    // rows touched: b down to r0-9, x/b up to r0+24; guard strips 0 and 31
    if ((r0 >= RSTRIP) && (r0 + 24 < GN))
        march<false>(xg, bg, og, r0, cbase, vs, lane);
    else
        march<true >(xg, bg, og, r0, cbase, vs, lane);
}

extern "C" void kernel_launch(void* const* d_in, const int* in_sizes, int n_in,
                              void* d_out, int out_size)
{
    const float* u = (const float*)d_in[0];
    const float* b = (const float*)d_in[1];
    float* out = (float*)d_out;

    dim3 block(128);                           // 4 independent warps (4 strips)
    dim3 grid(NSTRIPS / 4, NTILES, GBATCH);    // 8 x 5 x 16 = 640 blocks

    const int nfused = MAXITER / KFUSE;        // 5 launches, 4 sweeps each
    int prev_dst = -1;
    for (int f = 0; f < nfused; ++f) {
        int dst = ((nfused - 1 - f) & 1);              // last one lands in out
        int src = (f == 0) ? 0 : (prev_dst ? 1 : 2);
        jacobi4<<<grid, block>>>(u, b, out, src, dst);
        prev_dst = dst;
    }
}

// round 15
// speedup vs baseline: 1.5520x; 1.0537x over previous
#include <cuda_runtime.h>

#define GN 512
#define GBATCH 16
#define RSTRIP 8
#define NSTRIPS 64                // GN / RSTRIP
#define NTILES 5                  // windows at 0,96,192,288,384 (all in-grid)
#define MAXITER 20
#define KFUSE 4
#define WARMUP 9                  // level skew 2 -> first store at t=9
#define NSTEPS (RSTRIP + WARMUP)  // 17

// Scratch ping-pong buffer (16 MB) — __device__ global, no runtime allocation.
__device__ float g_scratch[GBATCH * GN * GN];

__device__ __forceinline__ float4 ld4(const float* p) {
    return *reinterpret_cast<const float4*>(p);
}
template<bool G>
__device__ __forceinline__ float4 ldx(const float* p, int row, int cbase) {
    if (G) return ((unsigned)row < GN) ? ld4(p + row * GN + cbase)
                                       : make_float4(0.f, 0.f, 0.f, 0.f);
    return ld4(p + row * GN + cbase);
}
__device__ __forceinline__ float4 scale4(float4 v) {
    v.x *= 0.25f; v.y *= 0.25f; v.z *= 0.25f; v.w *= 0.25f;
    return v;
}

// Jacobi row update; b4 PRE-SCALED by 0.25. Lane 0's left / lane 31's right
// neighbor is forced to 0: exact Dirichlet at grid-edge windows, harmless
// inside the >=4-col discard margin at internal window seams.
__device__ __forceinline__ float4 jrowf(float4 up, float4 mid, float4 dn,
                                        float4 b4, int lane)
{
    float l = __shfl_up_sync(0xffffffffu, mid.w, 1);
    float r = __shfl_down_sync(0xffffffffu, mid.x, 1);
    if (lane == 0)  l = 0.f;
    if (lane == 31) r = 0.f;
    float4 res;
    res.x = fmaf((l     + mid.y) + (up.x + dn.x), 0.25f, b4.x);
    res.y = fmaf((mid.x + mid.z) + (up.y + dn.y), 0.25f, b4.y);
    res.z = fmaf((mid.y + mid.w) + (up.z + dn.z), 0.25f, b4.z);
    res.w = fmaf((mid.z + r    ) + (up.w + dn.w), 0.25f, b4.w);
    return res;
}

// Level-skewed (skew 2) 4-deep Jacobi pipeline with 2-step load prefetch.
// At step t (a = r0-3+t): prefetch x[a+3], b[a+2] (used at t+2);
// L1 -> row a; L2 -> row a-2; L3 -> row a-4; L4 (store) -> row a-6 from
// t >= WARMUP. Lagged b rows (a-2, a-4, a-6) re-loaded from L1. All four
// level updates per step are mutually independent (inputs from steps <= t-1);
// Z-initialized rings feed only discarded rows.
// G=true adds two-sided row guards on loads and every level.
template<bool G>
__device__ __forceinline__ void march(const float* __restrict__ xg,
                                      const float* __restrict__ bg,
                                      float* __restrict__ og,
                                      int r0, int cbase, bool vs, int lane)
{
    const float4 Z = make_float4(0.f, 0.f, 0.f, 0.f);

    float4 xm  = ldx<G>(xg, r0 - 4, cbase);              // x row a-1 @ t=0
    float4 xc  = ldx<G>(xg, r0 - 3, cbase);              // x row a   @ t=0
    float4 xp0 = ldx<G>(xg, r0 - 2, cbase);              // x row a+1 for t=0
    float4 bb0 = scale4(ldx<G>(bg, r0 - 3, cbase));      // b row a   for t=0
    float4 xp1 = ldx<G>(xg, r0 - 1, cbase);              // for t=1
    float4 bb1 = scale4(ldx<G>(bg, r0 - 2, cbase));      // for t=1

    float4 p1b = Z, p1c = Z, p1d = Z;        // L1 rows a-1, a-2, a-3
    float4 p2b = Z, p2c = Z, p2d = Z;        // L2 rows a-3, a-4, a-5
    float4 p3b = Z, p3c = Z, p3d = Z;        // L3 rows a-5, a-6, a-7

    #pragma unroll
    for (int t = 0; t < NSTEPS; ++t) {
        const int a = r0 - 3 + t;

        // prefetch for step t+2 (issued ~2 steps before use)
        float4 xp2 = ldx<G>(xg, a + 3, cbase);
        float4 bb2 = scale4(ldx<G>(bg, a + 2, cbase));

        // lagged b rows from L1 (lines fetched by this warp steps ago)
        float4 b2 = scale4(ldx<G>(bg, a - 2, cbase));
        float4 b4 = scale4(ldx<G>(bg, a - 4, cbase));

        // four INDEPENDENT level updates (inputs all from steps <= t-1)
        float4 pn1 = (!G || (unsigned)a < GN)
                   ? jrowf(xm, xc, xp0, bb0, lane) : Z;        // L1 row a
        float4 pn2 = (!G || (unsigned)(a - 2) < GN)
                   ? jrowf(p1d, p1c, p1b, b2, lane) : Z;       // L2 row a-2
        float4 pn3 = (!G || (unsigned)(a - 4) < GN)
                   ? jrowf(p2d, p2c, p2b, b4, lane) : Z;       // L3 row a-4

        if (t >= WARMUP) {                                     // L4 row a-6
            float4 b6 = scale4(ldx<G>(bg, a - 6, cbase));
            float4 res = jrowf(p3d, p3c, p3b, b6, lane);
            if (vs) *reinterpret_cast<float4*>(og + (a - 6) * GN + cbase) = res;
        }

        // lockstep ring shifts (renamed by ptxas, no real MOVs)
        xm = xc; xc = xp0; xp0 = xp1; xp1 = xp2;
        bb0 = bb1; bb1 = bb2;
        p1d = p1c; p1c = p1b; p1b = pn1;
        p2d = p2c; p2c = p2b; p2b = pn2;
        p3d = p3c; p3c = p3b; p3b = pn3;
    }
}

// src_sel: 0 = u, 1 = g_scratch, 2 = out ; dst_sel: 0 = out, 1 = g_scratch
__global__ void __launch_bounds__(128, 5) jacobi4(
    const float* __restrict__ u,
    const float* __restrict__ b,
    float* __restrict__ out,
    int src_sel, int dst_sel)
{
    const float* x = (src_sel == 0) ? u
                   : (src_sel == 1) ? (const float*)g_scratch
                                    : (const float*)out;
    float* o = dst_sel ? g_scratch : out;

    const int lane  = threadIdx.x & 31;
    const int wid   = threadIdx.x >> 5;
    const int strip = blockIdx.x * 4 + wid;         // 0..63
    const int r0    = strip * RSTRIP;
    const int ty    = blockIdx.y;
    const int wb    = ty * 96;                      // window base: 0..384
    const int cbase = wb + lane * 4;                // ALWAYS in [0, 508]
    const int slo   = (ty == 0)          ? 0  : wb + 4;
    const int shi   = (ty == NTILES - 1) ? GN : wb + 100;
    const bool vs   = (cbase >= slo) && (cbase < shi);

    const size_t base = (size_t)blockIdx.z * (GN * GN);
    const float* xg = x + base;
    const float* bg = b + base;
    float*       og = o + base;

    // rows touched: b down to r0-9, x up to r0+16; guard strips 0,1,62,63
    if ((r0 >= 9) && (r0 + NSTEPS - 1 < GN))
        march<false>(xg, bg, og, r0, cbase, vs, lane);
    else
        march<true >(xg, bg, og, r0, cbase, vs, lane);
}

extern "C" void kernel_launch(void* const* d_in, const int* in_sizes, int n_in,
                              void* d_out, int out_size)
{
    const float* u = (const float*)d_in[0];
    const float* b = (const float*)d_in[1];
    float* out = (float*)d_out;

    dim3 block(128);                           // 4 independent warps (4 strips)
    dim3 grid(NSTRIPS / 4, NTILES, GBATCH);    // 16 x 5 x 16 = 1280 blocks

    const int nfused = MAXITER / KFUSE;        // 5 launches, 4 sweeps each
    int prev_dst = -1;
    for (int f = 0; f < nfused; ++f) {
        int dst = ((nfused - 1 - f) & 1);              // last one lands in out
        int src = (f == 0) ? 0 : (prev_dst ? 1 : 2);
        jacobi4<<<grid, block>>>(u, b, out, src, dst);
        prev_dst = dst;
    }
}